// round 2
// baseline (speedup 1.0000x reference)
#include <cuda_runtime.h>
#include <cuda_bf16.h>

#define N_NODES   100000
#define N_EDGES   3200000
#define IN_DIM    128
#define HID       64
#define OUT_DIM   128
#define N_GRAPHS  8

// ---------------- scratch (static __device__, no allocs) ----------------
__device__ float g_dinv[N_NODES];                       // deg, then dinv in-place
__device__ __align__(16) float g_bufA[N_NODES * HID];
__device__ __align__(16) float g_bufB[N_NODES * HID];
__device__ float g_pool[N_GRAPHS * HID];
__device__ float g_cnt[N_GRAPHS];

// ---------------- init: deg=1 (self loop), pool/cnt = 0 ----------------
__global__ void k_init(int n) {
    int i = blockIdx.x * blockDim.x + threadIdx.x;
    if (i < n) g_dinv[i] = 1.0f;
    if (i < N_GRAPHS * HID) g_pool[i] = 0.0f;
    if (i < N_GRAPHS) g_cnt[i] = 0.0f;
}

// ---------------- degree accumulate: deg[dst] += w ----------------
__global__ void k_degree(const int* __restrict__ dst,
                         const float* __restrict__ w, int E) {
    int e = blockIdx.x * blockDim.x + threadIdx.x;
    if (e >= E) return;
    atomicAdd(&g_dinv[dst[e]], w[e]);
}

// ---------------- deg -> rsqrt(deg) in place (deg >= 1 always) ----------------
__global__ void k_dinv(int n) {
    int i = blockIdx.x * blockDim.x + threadIdx.x;
    if (i < n) g_dinv[i] = rsqrtf(g_dinv[i]);
}

// ---------------- GEMM: Y[n x 64] = X[n x K] @ W[K x 64] ----------------
template <int K>
__global__ void k_gemm(const float* __restrict__ X, const float* __restrict__ W,
                       float* __restrict__ Y, int n) {
    __shared__ float Wsh[K * 64];
    __shared__ float Xsh[16 * K];
    int row0 = blockIdx.x * 16;

    for (int i = threadIdx.x; i < K * 64; i += 256) Wsh[i] = W[i];
    for (int i = threadIdx.x; i < 16 * K; i += 256) {
        int r = i / K, k = i % K;
        int gr = row0 + r;
        Xsh[i] = (gr < n) ? X[gr * K + k] : 0.0f;
    }
    __syncthreads();

    int c  = threadIdx.x & 63;
    int rg = threadIdx.x >> 6;        // 4 row-groups of 4 rows each
    const float* xp = &Xsh[(rg * 4) * K];
    float a0 = 0.f, a1 = 0.f, a2 = 0.f, a3 = 0.f;
#pragma unroll 8
    for (int k = 0; k < K; k++) {
        float wv = Wsh[k * 64 + c];
        a0 += xp[k]         * wv;
        a1 += xp[K + k]     * wv;
        a2 += xp[2 * K + k] * wv;
        a3 += xp[3 * K + k] * wv;
    }
    int row = row0 + rg * 4;
    if (row + 0 < n) Y[(row + 0) * 64 + c] = a0;
    if (row + 1 < n) Y[(row + 1) * 64 + c] = a1;
    if (row + 2 < n) Y[(row + 2) * 64 + c] = a2;
    if (row + 3 < n) Y[(row + 3) * 64 + c] = a3;
}

// ---------------- self-loop init: AGG = H * dinv^2 ----------------
__global__ void k_selfloop(const float* __restrict__ H, float* __restrict__ AGG, int n) {
    int i = blockIdx.x * blockDim.x + threadIdx.x;   // over n*16 float4
    if (i >= n * 16) return;
    int node = i >> 4;
    float dv = g_dinv[node];
    float s = dv * dv;
    float4 v = ((const float4*)H)[i];
    v.x *= s; v.y *= s; v.z *= s; v.w *= s;
    ((float4*)AGG)[i] = v;
}

// ---------------- edge scatter: AGG[dst] += H[src] * (dinv[s]*w*dinv[d]) ----------------
__global__ void k_scatter(const int* __restrict__ src,
                          const int* __restrict__ dst,
                          const float* __restrict__ w,
                          const float* __restrict__ H,
                          float* __restrict__ AGG, int E) {
    long long t = (long long)blockIdx.x * blockDim.x + threadIdx.x;
    int e = (int)(t >> 4);
    int lane = (int)(t & 15);
    if (e >= E) return;
    int s = src[e];
    int d = dst[e];
    float norm = g_dinv[s] * w[e] * g_dinv[d];
    float4 v = ((const float4*)H)[s * 16 + lane];
    v.x *= norm; v.y *= norm; v.z *= norm; v.w *= norm;
    float4* p = ((float4*)AGG) + d * 16 + lane;
    asm volatile("red.global.add.v4.f32 [%0], {%1, %2, %3, %4};"
                 :: "l"(p), "f"(v.x), "f"(v.y), "f"(v.z), "f"(v.w)
                 : "memory");
}

// ---------------- bias + relu: OUT = max(IN + b, 0) ----------------
__global__ void k_bias_relu(const float* __restrict__ IN, const float* __restrict__ b,
                            float* __restrict__ OUT, int n) {
    int i = blockIdx.x * blockDim.x + threadIdx.x;   // over n*16 float4
    if (i >= n * 16) return;
    float4 v = ((const float4*)IN)[i];
    float4 bb = ((const float4*)b)[i & 15];
    v.x = fmaxf(v.x + bb.x, 0.f);
    v.y = fmaxf(v.y + bb.y, 0.f);
    v.z = fmaxf(v.z + bb.z, 0.f);
    v.w = fmaxf(v.w + bb.w, 0.f);
    ((float4*)OUT)[i] = v;
}

// ---------------- pool: two-stage segment sum over batch ids ----------------
#define POOL_NB 512
__global__ void k_pool(const float* __restrict__ AGG,
                       const int* __restrict__ batch, int n) {
    __shared__ float acc[N_GRAPHS][HID];
    __shared__ float scnt[N_GRAPHS];
    for (int i = threadIdx.x; i < N_GRAPHS * HID; i += 256)
        acc[i / HID][i % HID] = 0.f;
    if (threadIdx.x < N_GRAPHS) scnt[threadIdx.x] = 0.f;
    __syncthreads();

    int c  = threadIdx.x & 63;
    int nl = threadIdx.x >> 6;    // 4 node lanes
    int base = blockIdx.x * POOL_NB;
    int lim = min(base + POOL_NB, n);
    for (int i = base + nl; i < lim; i += 4) {
        int b = batch[i];
        atomicAdd(&acc[b][c], AGG[i * 64 + c]);
        if (c == 0) atomicAdd(&scnt[b], 1.0f);
    }
    __syncthreads();
    for (int i = threadIdx.x; i < N_GRAPHS * HID; i += 256)
        atomicAdd(&g_pool[i], acc[i / HID][i % HID]);
    if (threadIdx.x < N_GRAPHS) atomicAdd(&g_cnt[threadIdx.x], scnt[threadIdx.x]);
}

// ---------------- final: out[g][o] = (pool[g]/cnt[g] + b2) @ Wfc + bfc ----------------
__global__ void k_final(const float* __restrict__ b2, const float* __restrict__ Wfc,
                        const float* __restrict__ bfc, float* __restrict__ out) {
    __shared__ float P[N_GRAPHS][HID];
    for (int i = threadIdx.x; i < N_GRAPHS * HID; i += 128) {
        int g = i / HID, c = i % HID;
        float cnt = fmaxf(g_cnt[g], 1.0f);
        P[g][c] = g_pool[i] / cnt + b2[c];
    }
    __syncthreads();
    int o = threadIdx.x;   // 128 threads
    for (int g = 0; g < N_GRAPHS; g++) {
        float s = bfc[o];
#pragma unroll
        for (int c = 0; c < HID; c++)
            s += P[g][c] * Wfc[c * OUT_DIM + o];
        out[g * OUT_DIM + o] = s;
    }
}

// ---------------- launcher ----------------
extern "C" void kernel_launch(void* const* d_in, const int* in_sizes, int n_in,
                              void* d_out, int out_size) {
    const float* x   = (const float*)d_in[0];
    const int*   ei  = (const int*)d_in[1];     // int64 inputs arrive as int32
    const float* ew  = (const float*)d_in[2];
    const int*   bat = (const int*)d_in[3];
    const float* W1  = (const float*)d_in[4];
    const float* b1  = (const float*)d_in[5];
    const float* W2  = (const float*)d_in[6];
    const float* b2  = (const float*)d_in[7];
    const float* Wfc = (const float*)d_in[8];
    const float* bfc = (const float*)d_in[9];
    float* out = (float*)d_out;

    int n = in_sizes[0] / IN_DIM;      // 100000
    int E = in_sizes[2];               // 3200000
    const int* src = ei;
    const int* dst = ei + E;

    float *bufA, *bufB;
    cudaGetSymbolAddress((void**)&bufA, g_bufA);
    cudaGetSymbolAddress((void**)&bufB, g_bufB);

    int ew_grid = (n * 16 + 255) / 256;                 // elementwise float4 grid
    long long sc = (long long)E * 16;
    int sc_grid = (int)((sc + 255) / 256);              // scatter grid

    // normalization
    k_init<<<(n + 255) / 256, 256>>>(n);
    k_degree<<<(E + 255) / 256, 256>>>(dst, ew, E);
    k_dinv<<<(n + 255) / 256, 256>>>(n);

    // conv1: h = x @ W1 ; agg = self + scatter ; relu(agg + b1) -> bufA
    k_gemm<IN_DIM><<<(n + 15) / 16, 256>>>(x, W1, bufA, n);
    k_selfloop<<<ew_grid, 256>>>(bufA, bufB, n);
    k_scatter<<<sc_grid, 256>>>(src, dst, ew, bufA, bufB, E);
    k_bias_relu<<<ew_grid, 256>>>(bufB, b1, bufA, n);

    // conv2: h2 = bufA @ W2 -> bufB ; agg -> bufA  (b2 folded into pooling epilogue)
    k_gemm<HID><<<(n + 15) / 16, 256>>>(bufA, W2, bufB, n);
    k_selfloop<<<ew_grid, 256>>>(bufB, bufA, n);
    k_scatter<<<sc_grid, 256>>>(src, dst, ew, bufB, bufA, E);

    // pool + fc
    k_pool<<<(n + POOL_NB - 1) / POOL_NB, 256>>>(bufA, bat, n);
    k_final<<<1, 128>>>(b2, Wfc, bfc, out);
}

// round 4
// speedup vs baseline: 1.4190x; 1.4190x over previous
#include <cuda_runtime.h>
#include <cuda_bf16.h>

#define N_NODES   100000
#define N_EDGES   3200000
#define IN_DIM    128
#define HID       64
#define OUT_DIM   128
#define N_GRAPHS  8
#define SCAN_B    1024

// ---------------- scratch (static __device__, no allocs) ----------------
__device__ float g_dinv[N_NODES];                       // wdeg then rsqrt in-place
__device__ int   g_cnt_e[N_NODES];                      // in-degree (edge count)
__device__ int   g_incl[N_NODES];                       // inclusive scan scratch
__device__ int   g_rowptr[N_NODES + 1];
__device__ int   g_fill[N_NODES];
__device__ int   g_bsum[256];
__device__ int   g_colsrc[N_EDGES];
__device__ float g_norm[N_EDGES];
__device__ __align__(16) float g_bufA[N_NODES * HID];
__device__ __align__(16) float g_bufB[N_NODES * HID];
__device__ float g_pool[N_GRAPHS * HID];
__device__ float g_cnt[N_GRAPHS];

// ---------------- init ----------------
__global__ void k_init0(int n) {
    int i = blockIdx.x * blockDim.x + threadIdx.x;
    if (i < n) {
        g_dinv[i]  = 1.0f;   // self-loop weight
        g_cnt_e[i] = 0;
        g_fill[i]  = 0;
    }
    if (i < N_GRAPHS * HID) g_pool[i] = 0.0f;
    if (i < N_GRAPHS) g_cnt[i] = 0.0f;
}

// ---------------- count: in-degree + weighted degree ----------------
__global__ void k_count(const int* __restrict__ dst,
                        const float* __restrict__ w, int E) {
    int e = blockIdx.x * blockDim.x + threadIdx.x;
    if (e >= E) return;
    int d = dst[e];
    atomicAdd(&g_cnt_e[d], 1);
    atomicAdd(&g_dinv[d], w[e]);
}

__global__ void k_dinv(int n) {
    int i = blockIdx.x * blockDim.x + threadIdx.x;
    if (i < n) g_dinv[i] = rsqrtf(g_dinv[i]);
}

// ---------------- scan stage A: per-1024 inclusive scan + block totals ----------------
__global__ void k_scanA(int n) {
    __shared__ int sh[256];
    int base = blockIdx.x * SCAN_B;
    int t = threadIdx.x;
    int v[4]; int s = 0;
#pragma unroll
    for (int j = 0; j < 4; j++) {
        int i = base + t * 4 + j;
        v[j] = (i < n) ? g_cnt_e[i] : 0;
        s += v[j];
    }
    sh[t] = s; __syncthreads();
    for (int off = 1; off < 256; off <<= 1) {
        int x = (t >= off) ? sh[t - off] : 0;
        __syncthreads();
        sh[t] += x;
        __syncthreads();
    }
    int run = sh[t] - s;
#pragma unroll
    for (int j = 0; j < 4; j++) {
        run += v[j];
        int i = base + t * 4 + j;
        if (i < n) g_incl[i] = run;
    }
    if (t == 255) g_bsum[blockIdx.x] = sh[255];
}

// ---------------- scan stage B: exclusive scan of block totals ----------------
__global__ void k_scanB(int nb) {
    __shared__ int sh[128];
    int t = threadIdx.x;
    int v = (t < nb) ? g_bsum[t] : 0;
    sh[t] = v; __syncthreads();
    for (int off = 1; off < 128; off <<= 1) {
        int x = (t >= off) ? sh[t - off] : 0;
        __syncthreads();
        sh[t] += x;
        __syncthreads();
    }
    if (t < nb) g_bsum[t] = sh[t] - v;
}

// ---------------- scan stage C: rowptr = exclusive prefix ----------------
__global__ void k_scanC(int n, int E) {
    int i = blockIdx.x * blockDim.x + threadIdx.x;
    if (i < n) g_rowptr[i] = g_incl[i] - g_cnt_e[i] + g_bsum[i >> 10];
    if (i == 0) g_rowptr[n] = E;
}

// ---------------- fill CSR (by dst) with precomputed norm ----------------
__global__ void k_fill(const int* __restrict__ src, const int* __restrict__ dst,
                       const float* __restrict__ w, int E) {
    int e = blockIdx.x * blockDim.x + threadIdx.x;
    if (e >= E) return;
    int s = src[e];
    int d = dst[e];
    int pos = g_rowptr[d] + atomicAdd(&g_fill[d], 1);
    g_colsrc[pos] = s;
    g_norm[pos] = g_dinv[s] * w[e] * g_dinv[d];
}

// ---------------- register-tiled GEMM: Y[n x 64] = X'[n x K] @ W[K x 64] ----
// X' = INRELU ? relu(X + b) : X. Tile 128 rows x 64 cols, thread = 4 rows x 8 cols.
template <int K, bool INRELU>
__global__ void k_gemm(const float* __restrict__ X, const float* __restrict__ W,
                       const float* __restrict__ bias, float* __restrict__ Y, int n) {
    __shared__ float Xs[128 * 33];
    __shared__ float Ws[32 * 64];

    int t = threadIdx.x;
    int row0 = blockIdx.x * 128;
    int tx = t & 7;          // col group: c0 = tx*8
    int ty = t >> 3;         // row group: r0 = ty*4
    int c0 = tx * 8;
    int r0 = ty * 4;

    float acc[4][8];
#pragma unroll
    for (int i = 0; i < 4; i++)
#pragma unroll
        for (int j = 0; j < 8; j++) acc[i][j] = 0.0f;

    for (int kc = 0; kc < K; kc += 32) {
        // load W chunk [32][64]
#pragma unroll
        for (int i = t; i < 32 * 64; i += 256) Ws[i] = W[(kc + (i >> 6)) * 64 + (i & 63)];
        // load X chunk [128][32] (padded 33)
#pragma unroll
        for (int i = t; i < 128 * 32; i += 256) {
            int r = i >> 5, k = i & 31;
            int gr = row0 + r;
            float v = (gr < n) ? X[gr * K + kc + k] : 0.0f;
            if (INRELU) v = fmaxf(v + __ldg(&bias[kc + k]), 0.0f);
            Xs[r * 33 + k] = v;
        }
        __syncthreads();

#pragma unroll
        for (int k = 0; k < 32; k++) {
            float xv[4];
#pragma unroll
            for (int i = 0; i < 4; i++) xv[i] = Xs[(r0 + i) * 33 + k];
            float4 w0 = *(const float4*)&Ws[k * 64 + c0];
            float4 w1 = *(const float4*)&Ws[k * 64 + c0 + 4];
            float wv[8] = {w0.x, w0.y, w0.z, w0.w, w1.x, w1.y, w1.z, w1.w};
#pragma unroll
            for (int i = 0; i < 4; i++)
#pragma unroll
                for (int j = 0; j < 8; j++) acc[i][j] += xv[i] * wv[j];
        }
        __syncthreads();
    }

#pragma unroll
    for (int i = 0; i < 4; i++) {
        int row = row0 + r0 + i;
        if (row < n) {
            float4 o0 = {acc[i][0], acc[i][1], acc[i][2], acc[i][3]};
            float4 o1 = {acc[i][4], acc[i][5], acc[i][6], acc[i][7]};
            *(float4*)&Y[row * 64 + c0]     = o0;
            *(float4*)&Y[row * 64 + c0 + 4] = o1;
        }
    }
}

// ---------------- gather conv: OUT[d] = dinv[d]^2*H[d] + sum_e norm[e]*H[src[e]] --
// one warp per node; half-warps process alternating edges; combine via shfl.
__global__ void k_gather(const float* __restrict__ H, float* __restrict__ OUT, int n) {
    int t = threadIdx.x;
    int lane = t & 15;            // feature float4 index
    int half = (t >> 4) & 1;      // 0/1: edge interleave
    int node = blockIdx.x * 8 + (t >> 5);
    if (node >= n) return;

    float4 acc = {0.f, 0.f, 0.f, 0.f};
    if (half == 0) {
        float dv = g_dinv[node];
        float s2 = dv * dv;
        float4 v = ((const float4*)H)[node * 16 + lane];
        acc.x = v.x * s2; acc.y = v.y * s2; acc.z = v.z * s2; acc.w = v.w * s2;
    }

    int beg = g_rowptr[node], end = g_rowptr[node + 1];
    int e = beg + half;
    // unroll-2 per half: up to 4 gathers in flight per warp
    for (; e + 2 < end; e += 4) {
        int s0 = g_colsrc[e];       float nv0 = g_norm[e];
        int s1 = g_colsrc[e + 2];   float nv1 = g_norm[e + 2];
        float4 v0 = ((const float4*)H)[s0 * 16 + lane];
        float4 v1 = ((const float4*)H)[s1 * 16 + lane];
        acc.x += nv0 * v0.x; acc.y += nv0 * v0.y; acc.z += nv0 * v0.z; acc.w += nv0 * v0.w;
        acc.x += nv1 * v1.x; acc.y += nv1 * v1.y; acc.z += nv1 * v1.z; acc.w += nv1 * v1.w;
    }
    for (; e < end; e += 2) {
        int s0 = g_colsrc[e]; float nv0 = g_norm[e];
        float4 v0 = ((const float4*)H)[s0 * 16 + lane];
        acc.x += nv0 * v0.x; acc.y += nv0 * v0.y; acc.z += nv0 * v0.z; acc.w += nv0 * v0.w;
    }

    // combine the two halves
    acc.x += __shfl_xor_sync(0xffffffffu, acc.x, 16);
    acc.y += __shfl_xor_sync(0xffffffffu, acc.y, 16);
    acc.z += __shfl_xor_sync(0xffffffffu, acc.z, 16);
    acc.w += __shfl_xor_sync(0xffffffffu, acc.w, 16);

    if (half == 0)
        ((float4*)OUT)[node * 16 + lane] = acc;
}

// ---------------- pool: two-stage segment sum over batch ids ----------------
#define POOL_NB 512
__global__ void k_pool(const float* __restrict__ AGG,
                       const int* __restrict__ batch, int n) {
    __shared__ float acc[N_GRAPHS][HID];
    __shared__ float scnt[N_GRAPHS];
    for (int i = threadIdx.x; i < N_GRAPHS * HID; i += 256)
        acc[i / HID][i % HID] = 0.f;
    if (threadIdx.x < N_GRAPHS) scnt[threadIdx.x] = 0.f;
    __syncthreads();

    int c  = threadIdx.x & 63;
    int nl = threadIdx.x >> 6;
    int base = blockIdx.x * POOL_NB;
    int lim = min(base + POOL_NB, n);
    for (int i = base + nl; i < lim; i += 4) {
        int b = batch[i];
        atomicAdd(&acc[b][c], AGG[i * 64 + c]);
        if (c == 0) atomicAdd(&scnt[b], 1.0f);
    }
    __syncthreads();
    for (int i = threadIdx.x; i < N_GRAPHS * HID; i += 256)
        atomicAdd(&g_pool[i], acc[i / HID][i % HID]);
    if (threadIdx.x < N_GRAPHS) atomicAdd(&g_cnt[threadIdx.x], scnt[threadIdx.x]);
}

// ---------------- final: out[g][o] = (pool[g]/cnt[g] + b2) @ Wfc + bfc ----------------
__global__ void k_final(const float* __restrict__ b2, const float* __restrict__ Wfc,
                        const float* __restrict__ bfc, float* __restrict__ out) {
    __shared__ float P[N_GRAPHS][HID];
    for (int i = threadIdx.x; i < N_GRAPHS * HID; i += 128) {
        int g = i / HID, c = i % HID;
        float cnt = fmaxf(g_cnt[g], 1.0f);
        P[g][c] = g_pool[i] / cnt + b2[c];
    }
    __syncthreads();
    int o = threadIdx.x;   // 128 threads
    for (int g = 0; g < N_GRAPHS; g++) {
        float s = bfc[o];
#pragma unroll
        for (int c = 0; c < HID; c++)
            s += P[g][c] * Wfc[c * OUT_DIM + o];
        out[g * OUT_DIM + o] = s;
    }
}

// ---------------- launcher ----------------
extern "C" void kernel_launch(void* const* d_in, const int* in_sizes, int n_in,
                              void* d_out, int out_size) {
    const float* x   = (const float*)d_in[0];
    const int*   ei  = (const int*)d_in[1];     // int64 inputs arrive as int32
    const float* ew  = (const float*)d_in[2];
    const int*   bat = (const int*)d_in[3];
    const float* W1  = (const float*)d_in[4];
    const float* b1  = (const float*)d_in[5];
    const float* W2  = (const float*)d_in[6];
    const float* b2  = (const float*)d_in[7];
    const float* Wfc = (const float*)d_in[8];
    const float* bfc = (const float*)d_in[9];
    float* out = (float*)d_out;

    int n = in_sizes[0] / IN_DIM;      // 100000
    int E = in_sizes[2];               // 3200000
    const int* src = ei;
    const int* dst = ei + E;

    float *bufA, *bufB;
    cudaGetSymbolAddress((void**)&bufA, g_bufA);
    cudaGetSymbolAddress((void**)&bufB, g_bufB);

    int nb = (n + SCAN_B - 1) / SCAN_B;           // 98 scan blocks
    int gE = (E + 255) / 256;
    int gN = (n + 255) / 256;

    // ---- CSR build (once per launch) ----
    k_init0<<<gN, 256>>>(n);
    k_count<<<gE, 256>>>(dst, ew, E);
    k_dinv<<<gN, 256>>>(n);
    k_scanA<<<nb, 256>>>(n);
    k_scanB<<<1, 128>>>(nb);
    k_scanC<<<gN, 256>>>(n, E);
    k_fill<<<gE, 256>>>(src, dst, ew, E);

    // ---- conv1: h1 = x @ W1 -> bufA ; agg1 -> bufB ----
    k_gemm<IN_DIM, false><<<(n + 127) / 128, 256>>>(x, W1, nullptr, bufA, n);
    k_gather<<<(n + 7) / 8, 256>>>(bufA, bufB, n);

    // ---- conv2: h2 = relu(agg1 + b1) @ W2 -> bufA ; agg2 -> bufB ----
    k_gemm<HID, true><<<(n + 127) / 128, 256>>>(bufB, W2, b1, bufA, n);
    k_gather<<<(n + 7) / 8, 256>>>(bufA, bufB, n);

    // ---- pool (b2 folded into final) + fc ----
    k_pool<<<(n + POOL_NB - 1) / POOL_NB, 256>>>(bufB, bat, n);
    k_final<<<1, 128>>>(b2, Wfc, bfc, out);
}

// round 6
// speedup vs baseline: 1.4520x; 1.0232x over previous
#include <cuda_runtime.h>
#include <cuda_fp16.h>
#include <cuda_bf16.h>

#define N_NODES   100000
#define N_EDGES   3200000
#define IN_DIM    128
#define HID       64
#define OUT_DIM   128
#define N_GRAPHS  8
#define SCAN_B    1024

// ---------------- scratch (static __device__, no allocs) ----------------
__device__ float g_dinv[N_NODES];                       // wdeg then rsqrt in-place
__device__ int   g_cnt_e[N_NODES];                      // in-degree (edge count)
__device__ int   g_incl[N_NODES];                       // inclusive scan scratch
__device__ int   g_rowptr[N_NODES + 1];
__device__ int   g_bsum[256];
__device__ int   g_epos[N_EDGES];                       // within-row position per edge
__device__ __align__(16) int2  g_edge[N_EDGES];         // {src, norm bits}
__device__ __align__(16) __half g_bufH[N_NODES * HID];  // fp16 h1 for gather1
__device__ __align__(16) float g_bufA[N_NODES * HID];
__device__ __align__(16) float g_bufB[N_NODES * HID];
__device__ float g_pool[N_GRAPHS * HID];
__device__ float g_cnt[N_GRAPHS];

// ---------------- init ----------------
__global__ void k_init0(int n) {
    int i = blockIdx.x * blockDim.x + threadIdx.x;
    if (i < n) {
        g_dinv[i]  = 1.0f;   // self-loop weight
        g_cnt_e[i] = 0;
    }
    if (i < N_GRAPHS * HID) g_pool[i] = 0.0f;
    if (i < N_GRAPHS) g_cnt[i] = 0.0f;
}

// ---------------- count: in-degree (capture position) + weighted degree ----------------
__global__ void k_count(const int* __restrict__ dst,
                        const float* __restrict__ w, int E) {
    int e = blockIdx.x * blockDim.x + threadIdx.x;
    if (e >= E) return;
    int d = dst[e];
    g_epos[e] = atomicAdd(&g_cnt_e[d], 1);
    atomicAdd(&g_dinv[d], w[e]);
}

// ---------------- scan stage A: per-1024 inclusive scan + block totals; fused rsqrt ----
__global__ void k_scanA(int n) {
    __shared__ int sh[256];
    int base = blockIdx.x * SCAN_B;
    int t = threadIdx.x;
    int v[4]; int s = 0;
#pragma unroll
    for (int j = 0; j < 4; j++) {
        int i = base + t * 4 + j;
        v[j] = (i < n) ? g_cnt_e[i] : 0;
        s += v[j];
        if (i < n) g_dinv[i] = rsqrtf(g_dinv[i]);
    }
    sh[t] = s; __syncthreads();
    for (int off = 1; off < 256; off <<= 1) {
        int x = (t >= off) ? sh[t - off] : 0;
        __syncthreads();
        sh[t] += x;
        __syncthreads();
    }
    int run = sh[t] - s;
#pragma unroll
    for (int j = 0; j < 4; j++) {
        run += v[j];
        int i = base + t * 4 + j;
        if (i < n) g_incl[i] = run;
    }
    if (t == 255) g_bsum[blockIdx.x] = sh[255];
}

// ---------------- scan stage B: exclusive scan of block totals ----------------
__global__ void k_scanB(int nb) {
    __shared__ int sh[128];
    int t = threadIdx.x;
    int v = (t < nb) ? g_bsum[t] : 0;
    sh[t] = v; __syncthreads();
    for (int off = 1; off < 128; off <<= 1) {
        int x = (t >= off) ? sh[t - off] : 0;
        __syncthreads();
        sh[t] += x;
        __syncthreads();
    }
    if (t < nb) g_bsum[t] = sh[t] - v;
}

// ---------------- scan stage C: rowptr = exclusive prefix ----------------
__global__ void k_scanC(int n, int E) {
    int i = blockIdx.x * blockDim.x + threadIdx.x;
    if (i < n) g_rowptr[i] = g_incl[i] - g_cnt_e[i] + g_bsum[i >> 10];
    if (i == 0) g_rowptr[n] = E;
}

// ---------------- fill CSR (by dst), atomic-free, fused norm ----------------
__global__ void k_fill(const int* __restrict__ src, const int* __restrict__ dst,
                       const float* __restrict__ w, int E) {
    int e = blockIdx.x * blockDim.x + threadIdx.x;
    if (e >= E) return;
    int s = src[e];
    int d = dst[e];
    int pos = g_rowptr[d] + g_epos[e];
    float norm = g_dinv[s] * w[e] * g_dinv[d];
    g_edge[pos] = make_int2(s, __float_as_int(norm));
}

// ---------------- register-tiled GEMM: Y[n x 64] = X'[n x K] @ W[K x 64] ----
// X' = INRELU ? relu(X + b) : X. Tile 128 rows x 64 cols, thread = 4 rows x 8 cols.
// OUTHALF: write Y as fp16 (half2-packed) instead of fp32.
template <int K, bool INRELU, bool OUTHALF>
__global__ void k_gemm(const float* __restrict__ X, const float* __restrict__ W,
                       const float* __restrict__ bias, void* __restrict__ Yv, int n) {
    __shared__ float Xs[128 * 33];
    __shared__ float Ws[32 * 64];

    int t = threadIdx.x;
    int row0 = blockIdx.x * 128;
    int tx = t & 7;          // col group: c0 = tx*8
    int ty = t >> 3;         // row group: r0 = ty*4
    int c0 = tx * 8;
    int r0 = ty * 4;

    float acc[4][8];
#pragma unroll
    for (int i = 0; i < 4; i++)
#pragma unroll
        for (int j = 0; j < 8; j++) acc[i][j] = 0.0f;

    for (int kc = 0; kc < K; kc += 32) {
#pragma unroll
        for (int i = t; i < 32 * 64; i += 256) Ws[i] = W[(kc + (i >> 6)) * 64 + (i & 63)];
#pragma unroll
        for (int i = t; i < 128 * 32; i += 256) {
            int r = i >> 5, k = i & 31;
            int gr = row0 + r;
            float v = (gr < n) ? X[gr * K + kc + k] : 0.0f;
            if (INRELU) v = fmaxf(v + __ldg(&bias[kc + k]), 0.0f);
            Xs[r * 33 + k] = v;
        }
        __syncthreads();

#pragma unroll
        for (int k = 0; k < 32; k++) {
            float xv[4];
#pragma unroll
            for (int i = 0; i < 4; i++) xv[i] = Xs[(r0 + i) * 33 + k];
            float4 w0 = *(const float4*)&Ws[k * 64 + c0];
            float4 w1 = *(const float4*)&Ws[k * 64 + c0 + 4];
            float wv[8] = {w0.x, w0.y, w0.z, w0.w, w1.x, w1.y, w1.z, w1.w};
#pragma unroll
            for (int i = 0; i < 4; i++)
#pragma unroll
                for (int j = 0; j < 8; j++) acc[i][j] += xv[i] * wv[j];
        }
        __syncthreads();
    }

#pragma unroll
    for (int i = 0; i < 4; i++) {
        int row = row0 + r0 + i;
        if (row < n) {
            if (OUTHALF) {
                __half2 h[4];
#pragma unroll
                for (int j = 0; j < 4; j++)
                    h[j] = __floats2half2_rn(acc[i][2 * j], acc[i][2 * j + 1]);
                *(uint4*)((__half*)Yv + row * 64 + c0) = *(uint4*)h;
            } else {
                float4 o0 = {acc[i][0], acc[i][1], acc[i][2], acc[i][3]};
                float4 o1 = {acc[i][4], acc[i][5], acc[i][6], acc[i][7]};
                *(float4*)((float*)Yv + row * 64 + c0)     = o0;
                *(float4*)((float*)Yv + row * 64 + c0 + 4) = o1;
            }
        }
    }
}

// ---------------- gather conv, fp16 H: OUT[d] = dinv^2*H[d] + sum norm*H[src] ----
// warp per node: 8 feature lanes (8 halfs = 16B each) x 4 edge slots.
__global__ void k_gather_h(const __half* __restrict__ H, float* __restrict__ OUT, int n) {
    int t = threadIdx.x;
    int fl   = t & 7;             // feature lane: halfs [fl*8, fl*8+8)
    int slot = (t >> 3) & 3;      // edge slot 0..3
    int node = blockIdx.x * 8 + (t >> 5);
    if (node >= n) return;

    const uint4* Hp = (const uint4*)H;   // 8 uint4 per row

    float f[8];
#pragma unroll
    for (int j = 0; j < 8; j++) f[j] = 0.0f;

    if (slot == 0) {
        float dv = g_dinv[node];
        float s2 = dv * dv;
        uint4 u = Hp[node * 8 + fl];
        const __half2* hp = (const __half2*)&u;
#pragma unroll
        for (int j = 0; j < 4; j++) {
            float2 v = __half22float2(hp[j]);
            f[2 * j]     = s2 * v.x;
            f[2 * j + 1] = s2 * v.y;
        }
    }

    int beg = g_rowptr[node], end = g_rowptr[node + 1];
    int e = beg + slot;
    for (; e + 4 < end; e += 8) {
        int2 e0 = g_edge[e];
        int2 e1 = g_edge[e + 4];
        uint4 u0 = Hp[e0.x * 8 + fl];
        uint4 u1 = Hp[e1.x * 8 + fl];
        float n0 = __int_as_float(e0.y);
        float n1 = __int_as_float(e1.y);
        const __half2* h0 = (const __half2*)&u0;
        const __half2* h1 = (const __half2*)&u1;
#pragma unroll
        for (int j = 0; j < 4; j++) {
            float2 v0 = __half22float2(h0[j]);
            float2 v1 = __half22float2(h1[j]);
            f[2 * j]     += n0 * v0.x + n1 * v1.x;
            f[2 * j + 1] += n0 * v0.y + n1 * v1.y;
        }
    }
    for (; e < end; e += 4) {
        int2 e0 = g_edge[e];
        uint4 u0 = Hp[e0.x * 8 + fl];
        float n0 = __int_as_float(e0.y);
        const __half2* h0 = (const __half2*)&u0;
#pragma unroll
        for (int j = 0; j < 4; j++) {
            float2 v0 = __half22float2(h0[j]);
            f[2 * j]     += n0 * v0.x;
            f[2 * j + 1] += n0 * v0.y;
        }
    }

    // reduce across the 4 edge slots (xor 8, xor 16)
#pragma unroll
    for (int off = 8; off < 32; off <<= 1)
#pragma unroll
        for (int j = 0; j < 8; j++)
            f[j] += __shfl_xor_sync(0xffffffffu, f[j], off);

    if (slot == 0) {
        float4 o0 = {f[0], f[1], f[2], f[3]};
        float4 o1 = {f[4], f[5], f[6], f[7]};
        *(float4*)&OUT[node * 64 + fl * 8]     = o0;
        *(float4*)&OUT[node * 64 + fl * 8 + 4] = o1;
    }
}

// ---------------- gather conv, fp32 H ----------------
// warp per node: 16 feature lanes (float4) x 2 edge halves, unroll 4.
__global__ void k_gather_f(const float* __restrict__ H, float* __restrict__ OUT, int n) {
    int t = threadIdx.x;
    int lane = t & 15;
    int half = (t >> 4) & 1;
    int node = blockIdx.x * 8 + (t >> 5);
    if (node >= n) return;

    float4 acc = {0.f, 0.f, 0.f, 0.f};
    if (half == 0) {
        float dv = g_dinv[node];
        float s2 = dv * dv;
        float4 v = ((const float4*)H)[node * 16 + lane];
        acc.x = v.x * s2; acc.y = v.y * s2; acc.z = v.z * s2; acc.w = v.w * s2;
    }

    int beg = g_rowptr[node], end = g_rowptr[node + 1];
    int e = beg + half;
    for (; e + 6 < end; e += 8) {
        int2 r0 = g_edge[e];
        int2 r1 = g_edge[e + 2];
        int2 r2 = g_edge[e + 4];
        int2 r3 = g_edge[e + 6];
        float4 v0 = ((const float4*)H)[r0.x * 16 + lane];
        float4 v1 = ((const float4*)H)[r1.x * 16 + lane];
        float4 v2 = ((const float4*)H)[r2.x * 16 + lane];
        float4 v3 = ((const float4*)H)[r3.x * 16 + lane];
        float n0 = __int_as_float(r0.y), n1 = __int_as_float(r1.y);
        float n2 = __int_as_float(r2.y), n3 = __int_as_float(r3.y);
        acc.x += n0 * v0.x + n1 * v1.x + n2 * v2.x + n3 * v3.x;
        acc.y += n0 * v0.y + n1 * v1.y + n2 * v2.y + n3 * v3.y;
        acc.z += n0 * v0.z + n1 * v1.z + n2 * v2.z + n3 * v3.z;
        acc.w += n0 * v0.w + n1 * v1.w + n2 * v2.w + n3 * v3.w;
    }
    for (; e < end; e += 2) {
        int2 r0 = g_edge[e];
        float4 v0 = ((const float4*)H)[r0.x * 16 + lane];
        float n0 = __int_as_float(r0.y);
        acc.x += n0 * v0.x; acc.y += n0 * v0.y; acc.z += n0 * v0.z; acc.w += n0 * v0.w;
    }

    acc.x += __shfl_xor_sync(0xffffffffu, acc.x, 16);
    acc.y += __shfl_xor_sync(0xffffffffu, acc.y, 16);
    acc.z += __shfl_xor_sync(0xffffffffu, acc.z, 16);
    acc.w += __shfl_xor_sync(0xffffffffu, acc.w, 16);

    if (half == 0)
        ((float4*)OUT)[node * 16 + lane] = acc;
}

// ---------------- pool: two-stage segment sum over batch ids ----------------
#define POOL_NB 512
__global__ void k_pool(const float* __restrict__ AGG,
                       const int* __restrict__ batch, int n) {
    __shared__ float acc[N_GRAPHS][HID];
    __shared__ float scnt[N_GRAPHS];
    for (int i = threadIdx.x; i < N_GRAPHS * HID; i += 256)
        acc[i / HID][i % HID] = 0.f;
    if (threadIdx.x < N_GRAPHS) scnt[threadIdx.x] = 0.f;
    __syncthreads();

    int c  = threadIdx.x & 63;
    int nl = threadIdx.x >> 6;
    int base = blockIdx.x * POOL_NB;
    int lim = min(base + POOL_NB, n);
    for (int i = base + nl; i < lim; i += 4) {
        int b = batch[i];
        atomicAdd(&acc[b][c], AGG[i * 64 + c]);
        if (c == 0) atomicAdd(&scnt[b], 1.0f);
    }
    __syncthreads();
    for (int i = threadIdx.x; i < N_GRAPHS * HID; i += 256)
        atomicAdd(&g_pool[i], acc[i / HID][i % HID]);
    if (threadIdx.x < N_GRAPHS) atomicAdd(&g_cnt[threadIdx.x], scnt[threadIdx.x]);
}

// ---------------- final: out[g][o] = (pool[g]/cnt[g] + b2) @ Wfc + bfc ----------------
__global__ void k_final(const float* __restrict__ b2, const float* __restrict__ Wfc,
                        const float* __restrict__ bfc, float* __restrict__ out) {
    __shared__ float P[N_GRAPHS][HID];
    for (int i = threadIdx.x; i < N_GRAPHS * HID; i += 128) {
        int g = i / HID, c = i % HID;
        float cnt = fmaxf(g_cnt[g], 1.0f);
        P[g][c] = g_pool[i] / cnt + b2[c];
    }
    __syncthreads();
    int o = threadIdx.x;   // 128 threads
    for (int g = 0; g < N_GRAPHS; g++) {
        float s = bfc[o];
#pragma unroll
        for (int c = 0; c < HID; c++)
            s += P[g][c] * Wfc[c * OUT_DIM + o];
        out[g * OUT_DIM + o] = s;
    }
}

// ---------------- launcher ----------------
extern "C" void kernel_launch(void* const* d_in, const int* in_sizes, int n_in,
                              void* d_out, int out_size) {
    const float* x   = (const float*)d_in[0];
    const int*   ei  = (const int*)d_in[1];     // int64 inputs arrive as int32
    const float* ew  = (const float*)d_in[2];
    const int*   bat = (const int*)d_in[3];
    const float* W1  = (const float*)d_in[4];
    const float* b1  = (const float*)d_in[5];
    const float* W2  = (const float*)d_in[6];
    const float* b2  = (const float*)d_in[7];
    const float* Wfc = (const float*)d_in[8];
    const float* bfc = (const float*)d_in[9];
    float* out = (float*)d_out;

    int n = in_sizes[0] / IN_DIM;      // 100000
    int E = in_sizes[2];               // 3200000
    const int* src = ei;
    const int* dst = ei + E;

    float *bufA, *bufB;
    __half* bufH;
    cudaGetSymbolAddress((void**)&bufA, g_bufA);
    cudaGetSymbolAddress((void**)&bufB, g_bufB);
    cudaGetSymbolAddress((void**)&bufH, g_bufH);

    int nb = (n + SCAN_B - 1) / SCAN_B;           // 98 scan blocks
    int gE = (E + 255) / 256;
    int gN = (n + 255) / 256;

    // ---- CSR build (once per launch) ----
    k_init0<<<gN, 256>>>(n);
    k_count<<<gE, 256>>>(dst, ew, E);
    k_scanA<<<nb, 256>>>(n);
    k_scanB<<<1, 128>>>(nb);
    k_scanC<<<gN, 256>>>(n, E);
    k_fill<<<gE, 256>>>(src, dst, ew, E);

    // ---- conv1: h1 = x @ W1 -> bufH (fp16) ; agg1 -> bufB (fp32) ----
    k_gemm<IN_DIM, false, true><<<(n + 127) / 128, 256>>>(x, W1, nullptr, bufH, n);
    k_gather_h<<<(n + 7) / 8, 256>>>(bufH, bufB, n);

    // ---- conv2: h2 = relu(agg1 + b1) @ W2 -> bufA ; agg2 -> bufB ----
    k_gemm<HID, true, false><<<(n + 127) / 128, 256>>>(bufB, W2, b1, bufA, n);
    k_gather_f<<<(n + 7) / 8, 256>>>(bufA, bufB, n);

    // ---- pool (b2 folded into final) + fc ----
    k_pool<<<(n + POOL_NB - 1) / POOL_NB, 256>>>(bufB, bat, n);
    k_final<<<1, 128>>>(b2, Wfc, bfc, out);
}

// round 9
// speedup vs baseline: 1.6224x; 1.1174x over previous
#include <cuda_runtime.h>
#include <cuda_fp16.h>
#include <cuda_bf16.h>

#define N_NODES   100000
#define N_EDGES   3200000
#define IN_DIM    128
#define HID       64
#define OUT_DIM   128
#define N_GRAPHS  8
#define SCAN_B    1024
#define WFIX      1048576.0f          // 2^20 fixed-point scale for weights

// ---------------- scratch (static __device__, no allocs) ----------------
__device__ unsigned long long g_pk[N_NODES];            // {count:24 | wsum.20fix:40}
__device__ float g_dinv[N_NODES];
__device__ int   g_cnt_e[N_NODES];
__device__ int   g_incl[N_NODES];
__device__ int   g_rowptr[N_NODES + 1];
__device__ int   g_bsum[256];
__device__ int   g_epos[N_EDGES];                       // within-row position per edge
__device__ __align__(16) int2  g_edge[N_EDGES];         // {src, norm bits}
__device__ __align__(16) __half g_bufH[N_NODES * HID];  // fp16 features for gathers
__device__ __align__(16) float g_bufA[N_NODES * HID];
__device__ __align__(16) float g_bufB[N_NODES * HID];
__device__ float g_pool[N_GRAPHS * HID];
__device__ float g_cnt[N_GRAPHS];

// ---------------- init: packed (count=0, wsum=1.0 for self loop) ----------------
__global__ void k_init0(int n) {
    int i = blockIdx.x * blockDim.x + threadIdx.x;
    if (i < n) g_pk[i] = (unsigned long long)(1u << 20);   // weight 1.0 fixed
    if (i < N_GRAPHS * HID) g_pool[i] = 0.0f;
    if (i < N_GRAPHS) g_cnt[i] = 0.0f;
}

// ---------------- count: ONE packed 64-bit atomic per edge ----------------
__global__ void k_count(const int* __restrict__ dst,
                        const float* __restrict__ w, int E) {
    int e = blockIdx.x * blockDim.x + threadIdx.x;
    if (e >= E) return;
    int d = dst[e];
    unsigned int wf = __float2uint_rn(w[e] * WFIX);
    unsigned long long inc = (1ULL << 40) | (unsigned long long)wf;
    unsigned long long old = atomicAdd(&g_pk[d], inc);
    g_epos[e] = (int)(old >> 40);
}

// ---------------- scan stage A: unpack pk -> cnt + dinv; inclusive scan ----------------
__global__ void k_scanA(int n) {
    __shared__ int sh[256];
    int base = blockIdx.x * SCAN_B;
    int t = threadIdx.x;
    int v[4]; int s = 0;
#pragma unroll
    for (int j = 0; j < 4; j++) {
        int i = base + t * 4 + j;
        int c = 0;
        if (i < n) {
            unsigned long long pk = g_pk[i];
            c = (int)(pk >> 40);
            float deg = (float)(pk & ((1ULL << 40) - 1)) * (1.0f / WFIX);
            g_dinv[i] = rsqrtf(deg);
            g_cnt_e[i] = c;
        }
        v[j] = c;
        s += c;
    }
    sh[t] = s; __syncthreads();
    for (int off = 1; off < 256; off <<= 1) {
        int x = (t >= off) ? sh[t - off] : 0;
        __syncthreads();
        sh[t] += x;
        __syncthreads();
    }
    int run = sh[t] - s;
#pragma unroll
    for (int j = 0; j < 4; j++) {
        run += v[j];
        int i = base + t * 4 + j;
        if (i < n) g_incl[i] = run;
    }
    if (t == 255) g_bsum[blockIdx.x] = sh[255];
}

// ---------------- scan stage B: exclusive scan of block totals ----------------
__global__ void k_scanB(int nb) {
    __shared__ int sh[128];
    int t = threadIdx.x;
    int v = (t < nb) ? g_bsum[t] : 0;
    sh[t] = v; __syncthreads();
    for (int off = 1; off < 128; off <<= 1) {
        int x = (t >= off) ? sh[t - off] : 0;
        __syncthreads();
        sh[t] += x;
        __syncthreads();
    }
    if (t < nb) g_bsum[t] = sh[t] - v;
}

// ---------------- scan stage C: rowptr = exclusive prefix ----------------
__global__ void k_scanC(int n, int E) {
    int i = blockIdx.x * blockDim.x + threadIdx.x;
    if (i < n) g_rowptr[i] = g_incl[i] - g_cnt_e[i] + g_bsum[i >> 10];
    if (i == 0) g_rowptr[n] = E;
}

// ---------------- fill CSR (by dst), atomic-free, fused norm ----------------
__global__ void k_fill(const int* __restrict__ src, const int* __restrict__ dst,
                       const float* __restrict__ w, int E) {
    int e = blockIdx.x * blockDim.x + threadIdx.x;
    if (e >= E) return;
    int s = src[e];
    int d = dst[e];
    int pos = g_rowptr[d] + g_epos[e];
    float norm = g_dinv[s] * w[e] * g_dinv[d];
    g_edge[pos] = make_int2(s, __float_as_int(norm));
}

// ---------------- register-tiled GEMM: Y[n x 64] = X'[n x K] @ W[K x 64] ----
// X' = INRELU ? relu(X + b) : X. Tile 128 rows x 64 cols, thread = 4 rows x 8 cols.
// OUTHALF: write Y as fp16 (half2-packed) instead of fp32.
template <int K, bool INRELU, bool OUTHALF>
__global__ void k_gemm(const float* __restrict__ X, const float* __restrict__ W,
                       const float* __restrict__ bias, void* __restrict__ Yv, int n) {
    __shared__ float Xs[128 * 33];
    __shared__ float Ws[32 * 64];

    int t = threadIdx.x;
    int row0 = blockIdx.x * 128;
    int tx = t & 7;
    int ty = t >> 3;
    int c0 = tx * 8;
    int r0 = ty * 4;

    float acc[4][8];
#pragma unroll
    for (int i = 0; i < 4; i++)
#pragma unroll
        for (int j = 0; j < 8; j++) acc[i][j] = 0.0f;

    for (int kc = 0; kc < K; kc += 32) {
#pragma unroll
        for (int i = t; i < 32 * 64; i += 256) Ws[i] = W[(kc + (i >> 6)) * 64 + (i & 63)];
#pragma unroll
        for (int i = t; i < 128 * 32; i += 256) {
            int r = i >> 5, k = i & 31;
            int gr = row0 + r;
            float v = (gr < n) ? X[gr * K + kc + k] : 0.0f;
            if (INRELU) v = fmaxf(v + __ldg(&bias[kc + k]), 0.0f);
            Xs[r * 33 + k] = v;
        }
        __syncthreads();

#pragma unroll
        for (int k = 0; k < 32; k++) {
            float xv[4];
#pragma unroll
            for (int i = 0; i < 4; i++) xv[i] = Xs[(r0 + i) * 33 + k];
            float4 w0 = *(const float4*)&Ws[k * 64 + c0];
            float4 w1 = *(const float4*)&Ws[k * 64 + c0 + 4];
            float wv[8] = {w0.x, w0.y, w0.z, w0.w, w1.x, w1.y, w1.z, w1.w};
#pragma unroll
            for (int i = 0; i < 4; i++)
#pragma unroll
                for (int j = 0; j < 8; j++) acc[i][j] += xv[i] * wv[j];
        }
        __syncthreads();
    }

#pragma unroll
    for (int i = 0; i < 4; i++) {
        int row = row0 + r0 + i;
        if (row < n) {
            if (OUTHALF) {
                __half2 h[4];
#pragma unroll
                for (int j = 0; j < 4; j++)
                    h[j] = __floats2half2_rn(acc[i][2 * j], acc[i][2 * j + 1]);
                *(uint4*)((__half*)Yv + row * 64 + c0) = *(uint4*)h;
            } else {
                float4 o0 = {acc[i][0], acc[i][1], acc[i][2], acc[i][3]};
                float4 o1 = {acc[i][4], acc[i][5], acc[i][6], acc[i][7]};
                *(float4*)((float*)Yv + row * 64 + c0)     = o0;
                *(float4*)((float*)Yv + row * 64 + c0 + 4) = o1;
            }
        }
    }
}

// ---------------- gather conv, fp16 H: OUT[d] = dinv^2*H[d] + sum norm*H[src] ----
// warp per node: 8 feature lanes (8 halfs = 16B each) x 4 edge slots.
__global__ void k_gather_h(const __half* __restrict__ H, float* __restrict__ OUT, int n) {
    int t = threadIdx.x;
    int fl   = t & 7;             // feature lane: halfs [fl*8, fl*8+8)
    int slot = (t >> 3) & 3;      // edge slot 0..3
    int node = blockIdx.x * 8 + (t >> 5);
    if (node >= n) return;

    const uint4* Hp = (const uint4*)H;   // 8 uint4 per row

    float f[8];
#pragma unroll
    for (int j = 0; j < 8; j++) f[j] = 0.0f;

    if (slot == 0) {
        float dv = g_dinv[node];
        float s2 = dv * dv;
        uint4 u = Hp[node * 8 + fl];
        const __half2* hp = (const __half2*)&u;
#pragma unroll
        for (int j = 0; j < 4; j++) {
            float2 v = __half22float2(hp[j]);
            f[2 * j]     = s2 * v.x;
            f[2 * j + 1] = s2 * v.y;
        }
    }

    int beg = g_rowptr[node], end = g_rowptr[node + 1];
    int e = beg + slot;
    for (; e + 4 < end; e += 8) {
        int2 e0 = g_edge[e];
        int2 e1 = g_edge[e + 4];
        uint4 u0 = Hp[e0.x * 8 + fl];
        uint4 u1 = Hp[e1.x * 8 + fl];
        float n0 = __int_as_float(e0.y);
        float n1 = __int_as_float(e1.y);
        const __half2* h0 = (const __half2*)&u0;
        const __half2* h1 = (const __half2*)&u1;
#pragma unroll
        for (int j = 0; j < 4; j++) {
            float2 v0 = __half22float2(h0[j]);
            float2 v1 = __half22float2(h1[j]);
            f[2 * j]     += n0 * v0.x + n1 * v1.x;
            f[2 * j + 1] += n0 * v0.y + n1 * v1.y;
        }
    }
    for (; e < end; e += 4) {
        int2 e0 = g_edge[e];
        uint4 u0 = Hp[e0.x * 8 + fl];
        float n0 = __int_as_float(e0.y);
        const __half2* h0 = (const __half2*)&u0;
#pragma unroll
        for (int j = 0; j < 4; j++) {
            float2 v0 = __half22float2(h0[j]);
            f[2 * j]     += n0 * v0.x;
            f[2 * j + 1] += n0 * v0.y;
        }
    }

    // reduce across the 4 edge slots (xor 8, xor 16)
#pragma unroll
    for (int off = 8; off < 32; off <<= 1)
#pragma unroll
        for (int j = 0; j < 8; j++)
            f[j] += __shfl_xor_sync(0xffffffffu, f[j], off);

    if (slot == 0) {
        float4 o0 = {f[0], f[1], f[2], f[3]};
        float4 o1 = {f[4], f[5], f[6], f[7]};
        *(float4*)&OUT[node * 64 + fl * 8]     = o0;
        *(float4*)&OUT[node * 64 + fl * 8 + 4] = o1;
    }
}

// ---------------- pool: two-stage segment sum over batch ids ----------------
#define POOL_NB 512
__global__ void k_pool(const float* __restrict__ AGG,
                       const int* __restrict__ batch, int n) {
    __shared__ float acc[N_GRAPHS][HID];
    __shared__ float scnt[N_GRAPHS];
    for (int i = threadIdx.x; i < N_GRAPHS * HID; i += 256)
        acc[i / HID][i % HID] = 0.f;
    if (threadIdx.x < N_GRAPHS) scnt[threadIdx.x] = 0.f;
    __syncthreads();

    int c  = threadIdx.x & 63;
    int nl = threadIdx.x >> 6;
    int base = blockIdx.x * POOL_NB;
    int lim = min(base + POOL_NB, n);
    for (int i = base + nl; i < lim; i += 4) {
        int b = batch[i];
        atomicAdd(&acc[b][c], AGG[i * 64 + c]);
        if (c == 0) atomicAdd(&scnt[b], 1.0f);
    }
    __syncthreads();
    for (int i = threadIdx.x; i < N_GRAPHS * HID; i += 256)
        atomicAdd(&g_pool[i], acc[i / HID][i % HID]);
    if (threadIdx.x < N_GRAPHS) atomicAdd(&g_cnt[threadIdx.x], scnt[threadIdx.x]);
}

// ---------------- final: out[g][o] = (pool[g]/cnt[g] + b2) @ Wfc + bfc ----------------
__global__ void k_final(const float* __restrict__ b2, const float* __restrict__ Wfc,
                        const float* __restrict__ bfc, float* __restrict__ out) {
    __shared__ float P[N_GRAPHS][HID];
    for (int i = threadIdx.x; i < N_GRAPHS * HID; i += 128) {
        int g = i / HID, c = i % HID;
        float cnt = fmaxf(g_cnt[g], 1.0f);
        P[g][c] = g_pool[i] / cnt + b2[c];
    }
    __syncthreads();
    int o = threadIdx.x;   // 128 threads
    for (int g = 0; g < N_GRAPHS; g++) {
        float s = bfc[o];
#pragma unroll
        for (int c = 0; c < HID; c++)
            s += P[g][c] * Wfc[c * OUT_DIM + o];
        out[g * OUT_DIM + o] = s;
    }
}

// ---------------- launcher ----------------
extern "C" void kernel_launch(void* const* d_in, const int* in_sizes, int n_in,
                              void* d_out, int out_size) {
    const float* x   = (const float*)d_in[0];
    const int*   ei  = (const int*)d_in[1];     // int64 inputs arrive as int32
    const float* ew  = (const float*)d_in[2];
    const int*   bat = (const int*)d_in[3];
    const float* W1  = (const float*)d_in[4];
    const float* b1  = (const float*)d_in[5];
    const float* W2  = (const float*)d_in[6];
    const float* b2  = (const float*)d_in[7];
    const float* Wfc = (const float*)d_in[8];
    const float* bfc = (const float*)d_in[9];
    float* out = (float*)d_out;

    int n = in_sizes[0] / IN_DIM;      // 100000
    int E = in_sizes[2];               // 3200000
    const int* src = ei;
    const int* dst = ei + E;

    float *bufA, *bufB;
    __half* bufH;
    cudaGetSymbolAddress((void**)&bufA, g_bufA);
    cudaGetSymbolAddress((void**)&bufB, g_bufB);
    cudaGetSymbolAddress((void**)&bufH, g_bufH);

    int nb = (n + SCAN_B - 1) / SCAN_B;           // 98 scan blocks
    int gE = (E + 255) / 256;
    int gN = (n + 255) / 256;

    // ---- CSR build (once per launch) ----
    k_init0<<<gN, 256>>>(n);
    k_count<<<gE, 256>>>(dst, ew, E);
    k_scanA<<<nb, 256>>>(n);
    k_scanB<<<1, 128>>>(nb);
    k_scanC<<<gN, 256>>>(n, E);
    k_fill<<<gE, 256>>>(src, dst, ew, E);

    // ---- conv1: h1 = x @ W1 -> bufH (fp16) ; agg1 -> bufB (fp32) ----
    k_gemm<IN_DIM, false, true><<<(n + 127) / 128, 256>>>(x, W1, nullptr, bufH, n);
    k_gather_h<<<(n + 7) / 8, 256>>>(bufH, bufB, n);

    // ---- conv2: h2 = relu(agg1 + b1) @ W2 -> bufH (fp16) ; agg2 -> bufA ----
    k_gemm<HID, true, true><<<(n + 127) / 128, 256>>>(bufB, W2, b1, bufH, n);
    k_gather_h<<<(n + 7) / 8, 256>>>(bufH, bufA, n);

    // ---- pool (b2 folded into final) + fc ----
    k_pool<<<(n + POOL_NB - 1) / POOL_NB, 256>>>(bufA, bat, n);
    k_final<<<1, 128>>>(b2, Wfc, bfc, out);
}